// round 13
// baseline (speedup 1.0000x reference)
#include <cuda_runtime.h>
#include <math.h>

// Problem constants
#define T_STEPS 16384
#define HDIM    1024
#define XDIM    256

// Recurrent kernel config (R3-proven compute topology)
#define NCTA          128   // persistent CTAs (co-resident in wave 1)
#define ROWS_PER_CTA  8     // HDIM / NCTA
#define RNN_THREADS   256   // 8 warps, one row per warp
#define NRELAY        8     // relay CTAs (b % 16 == 0), 16 members each
#define LINE_INTS     32    // one word per 128B line
#define WATCHDOG_POLLS (1 << 21)   // ~0.4 s of tight polling before abort

// Scratch (device globals: allocation-free per harness rules)
__device__ float g_bx[(size_t)T_STEPS * HDIM];       // Bx_c, 64 MB
__device__ int   g_cnt0;                             // single monotonic counter
__device__ int   g_relay[NRELAY * LINE_INTS];        // 8 private relay words
__device__ int   g_member[NCTA * LINE_INTS];         // 128 private member words
__device__ int   g_abort;

// ---------------------------------------------------------------------------
// helpers
// ---------------------------------------------------------------------------
__device__ __forceinline__ int atom_acqrel_add(int* p, int v) {
    int old;
    asm volatile("atom.acq_rel.gpu.global.add.s32 %0, [%1], %2;"
                 : "=r"(old) : "l"(p), "r"(v) : "memory");
    return old;
}

__device__ __forceinline__ int ldcg_i32(const int* p) {
    int v;
    asm volatile("ld.global.cg.s32 %0, [%1];" : "=r"(v) : "l"(p) : "memory");
    return v;
}

__device__ __forceinline__ void stg_i32(int* p, int v) {
    asm volatile("st.global.s32 [%0], %1;" :: "l"(p), "r"(v) : "memory");
}

__device__ __forceinline__ void fence_acq() {
    asm volatile("fence.acq_rel.gpu;" ::: "memory");
}

__device__ __forceinline__ float warp_sum(float v) {
#pragma unroll
    for (int s = 16; s > 0; s >>= 1)
        v += __shfl_xor_sync(0xffffffffu, v, s);
    return v;
}

__device__ __forceinline__ float fast_tanh(float x) {
    // tanh(x) = 1 - 2/(exp(2x)+1); MUFU-based, ~1e-6 rel error (validated R11).
    return 1.0f - __fdividef(2.0f, __expf(2.0f * x) + 1.0f);
}

// ---------------------------------------------------------------------------
// 0) zero sync state (graph replays reuse device globals -> re-init)
// ---------------------------------------------------------------------------
__global__ void init_cnt_kernel() {
    int i = blockIdx.x * blockDim.x + threadIdx.x;
    if (i == 0) { g_cnt0 = 0; g_abort = 0; }
    if (i < NRELAY * LINE_INTS) g_relay[i] = 0;
    if (i < NCTA * LINE_INTS)   g_member[i] = 0;
}

// ---------------------------------------------------------------------------
// 1) Bx_c = x_seq @ B^T + c   (T x H), fp32 tiled GEMM
// ---------------------------------------------------------------------------
__global__ __launch_bounds__(256) void gemm_bx_kernel(
    const float* __restrict__ x,   // (T, 256)
    const float* __restrict__ B,   // (1024, 256)
    const float* __restrict__ c)   // (1024,)
{
    __shared__ float xsT[32][132];
    __shared__ float bsT[32][68];

    const int bj  = blockIdx.x * 64;
    const int bt  = blockIdx.y * 128;
    const int tid = threadIdx.x;
    const int tx  = tid & 15;
    const int ty  = tid >> 4;

    float acc[8][4];
#pragma unroll
    for (int i = 0; i < 8; i++)
#pragma unroll
        for (int j = 0; j < 4; j++) acc[i][j] = 0.0f;

    for (int k0 = 0; k0 < XDIM; k0 += 32) {
#pragma unroll
        for (int i = 0; i < 4; i++) {
            int idx = tid + i * 256;
            int r   = idx >> 3;
            int kk4 = (idx & 7) * 4;
            float4 v = *(const float4*)&x[(size_t)(bt + r) * XDIM + k0 + kk4];
            xsT[kk4 + 0][r] = v.x; xsT[kk4 + 1][r] = v.y;
            xsT[kk4 + 2][r] = v.z; xsT[kk4 + 3][r] = v.w;
        }
#pragma unroll
        for (int i = 0; i < 2; i++) {
            int idx = tid + i * 256;
            int r   = idx >> 3;
            int kk4 = (idx & 7) * 4;
            float4 v = *(const float4*)&B[(size_t)(bj + r) * XDIM + k0 + kk4];
            bsT[kk4 + 0][r] = v.x; bsT[kk4 + 1][r] = v.y;
            bsT[kk4 + 2][r] = v.z; bsT[kk4 + 3][r] = v.w;
        }
        __syncthreads();

#pragma unroll
        for (int kk = 0; kk < 32; kk++) {
            float xr[8], br[4];
#pragma unroll
            for (int i = 0; i < 8; i++) xr[i] = xsT[kk][ty * 8 + i];
#pragma unroll
            for (int j = 0; j < 4; j++) br[j] = bsT[kk][tx * 4 + j];
#pragma unroll
            for (int i = 0; i < 8; i++)
#pragma unroll
                for (int j = 0; j < 4; j++)
                    acc[i][j] = fmaf(xr[i], br[j], acc[i][j]);
        }
        __syncthreads();
    }

#pragma unroll
    for (int i = 0; i < 8; i++) {
        int t = bt + ty * 8 + i;
#pragma unroll
        for (int j = 0; j < 4; j++) {
            int col = bj + tx * 4 + j;
            g_bx[(size_t)t * HDIM + col] = acc[i][j] + c[col];
        }
    }
}

// ---------------------------------------------------------------------------
// 2) persistent recurrent kernel: winner-detect + private-line fan-out.
//    Publish: STG h -> bar -> atom.acq_rel.add(g_cnt0, 1).
//    Winner (old == 128t+127) -> fence -> STG t+1 to 8 relay words.
//    Relays (b%16==0) tight-poll THEIR OWN word (1 reader/line: no
//    starvation, ~170cyc detect) -> fence -> STG t+1 to 16 member words.
//    Members tight-poll their own word -> fence. Sync happens at END of
//    step t; step t+1 then reads out[t].
// ---------------------------------------------------------------------------
__global__ __launch_bounds__(RNN_THREADS, 1) void rnn_scan_kernel(
    const float* __restrict__ A_raw,  // (1024, 1024)
    const float* __restrict__ h0,     // (1024,)
    float* __restrict__ out)          // (16384, 1024)
{
    __shared__ int s_abort;
    const int b   = blockIdx.x;
    const int w   = threadIdx.x >> 5;
    const int l   = threadIdx.x & 31;
    const int row = b * ROWS_PER_CTA + w;
    const bool is_relay = ((b & 15) == 0);

    if (threadIdx.x == 0) s_abort = 0;

    // Load A row segment into registers, applying A = 0.9*I + 0.1*A_raw
    float4 a[8];
#pragma unroll
    for (int i = 0; i < 8; i++) {
        int col  = 32 * l + 4 * i;
        float4 v = *(const float4*)&A_raw[(size_t)row * HDIM + col];
        v.x *= 0.1f; v.y *= 0.1f; v.z *= 0.1f; v.w *= 0.1f;
        int d = row - col;
        if (d == 0) v.x += 0.9f;
        else if (d == 1) v.y += 0.9f;
        else if (d == 2) v.z += 0.9f;
        else if (d == 3) v.w += 0.9f;
        a[i] = v;
    }
    __syncthreads();

    const float* hprev = h0;

    for (int t = 0; t < T_STEPS; t++) {
        // bias prefetch (independent of h)
        float bxv = 0.0f;
        if (l == 0) bxv = g_bx[(size_t)t * HDIM + row];

        // dot product: 32 contiguous elements per lane
        const float4* h4 = (const float4*)(hprev + 32 * l);
        float a0 = 0.f, a1 = 0.f, a2 = 0.f, a3 = 0.f;
#pragma unroll
        for (int i = 0; i < 8; i++) {
            float4 hv = h4[i];
            a0 = fmaf(a[i].x, hv.x, a0);
            a1 = fmaf(a[i].y, hv.y, a1);
            a2 = fmaf(a[i].z, hv.z, a2);
            a3 = fmaf(a[i].w, hv.w, a3);
        }
        float acc = warp_sum((a0 + a1) + (a2 + a3));

        if (l == 0) {
            out[(size_t)t * HDIM + row] = fast_tanh(acc + bxv);
        }

        __syncthreads();   // all 8 rows of out[t] stored

        // ---- end-of-step barrier ----
        if (threadIdx.x == 0) {
            const int gate = t + 1;

            // arrival (release: h stores ordered before the add)
            int old = atom_acqrel_add(&g_cnt0, 1);
            if (old == NCTA * t + (NCTA - 1)) {
                // winner: saw all arrivals (acquire) -> fan out to relays
                fence_acq();
#pragma unroll
                for (int r = 0; r < NRELAY; r++)
                    stg_i32(&g_relay[r * LINE_INTS], gate);
            }

            if (is_relay) {
                // tight poll own relay word (single reader per line)
                const int* rp = &g_relay[(b >> 4) * LINE_INTS];
                int polls = 0;
                for (;;) {
                    if (ldcg_i32(rp) >= gate) break;
                    if ((++polls & 255) == 0) {
                        if (ldcg_i32(&g_abort) || polls > WATCHDOG_POLLS) {
                            stg_i32(&g_abort, 1);
                            s_abort = 1;
                            break;
                        }
                    }
                }
                if (!s_abort) {
                    fence_acq();
#pragma unroll
                    for (int m = 0; m < 16; m++)
                        stg_i32(&g_member[(b + m) * LINE_INTS], gate);
                }
            } else {
                // tight poll own member word (single reader per line)
                const int* mp = &g_member[b * LINE_INTS];
                int polls = 0;
                for (;;) {
                    if (ldcg_i32(mp) >= gate) break;
                    if ((++polls & 255) == 0) {
                        if (ldcg_i32(&g_abort) || polls > WATCHDOG_POLLS) {
                            stg_i32(&g_abort, 1);
                            s_abort = 1;
                            break;
                        }
                    }
                }
                if (!s_abort) fence_acq();
            }
        }
        __syncthreads();
        if (s_abort) return;   // uniform exit: fallback recomputes

        hprev = out + (size_t)t * HDIM;
    }
}

// ---------------------------------------------------------------------------
// 3) fallback: single-CTA full recompute; runs only if g_abort was set.
// ---------------------------------------------------------------------------
__global__ __launch_bounds__(1024) void fallback_scan_kernel(
    const float* __restrict__ A_raw,
    const float* __restrict__ h0,
    float* __restrict__ out)
{
    if (g_abort == 0) return;

    __shared__ float h[HDIM];
    __shared__ float hn[HDIM];
    const int tid = threadIdx.x;
    const int w   = tid >> 5;
    const int l   = tid & 31;

    h[tid] = h0[tid];
    __syncthreads();

    for (int t = 0; t < T_STEPS; t++) {
        for (int r = w; r < HDIM; r += 32) {
            const float* Ar = A_raw + (size_t)r * HDIM;
            float acc = 0.0f;
#pragma unroll 8
            for (int k = l; k < HDIM; k += 32)
                acc = fmaf(Ar[k], h[k], acc);
#pragma unroll
            for (int s = 16; s > 0; s >>= 1)
                acc += __shfl_xor_sync(0xffffffffu, acc, s);
            if (l == 0) {
                float v = tanhf(0.1f * acc + 0.9f * h[r] +
                                g_bx[(size_t)t * HDIM + r]);
                hn[r] = v;
                out[(size_t)t * HDIM + r] = v;
            }
        }
        __syncthreads();
        h[tid] = hn[tid];
        __syncthreads();
    }
}

// ---------------------------------------------------------------------------
// launch
// ---------------------------------------------------------------------------
extern "C" void kernel_launch(void* const* d_in, const int* in_sizes, int n_in,
                              void* d_out, int out_size) {
    const float* x_seq = (const float*)d_in[0];  // (16384, 256)
    const float* h0    = (const float*)d_in[1];  // (1024,)
    const float* A_raw = (const float*)d_in[2];  // (1024, 1024)
    const float* B     = (const float*)d_in[3];  // (1024, 256)
    const float* c     = (const float*)d_in[4];  // (1024,)
    float* out = (float*)d_out;                  // (16384, 1024)

    init_cnt_kernel<<<8, 1024>>>();
    gemm_bx_kernel<<<dim3(HDIM / 64, T_STEPS / 128), 256>>>(x_seq, B, c);
    rnn_scan_kernel<<<NCTA, RNN_THREADS>>>(A_raw, h0, out);
    fallback_scan_kernel<<<1, 1024>>>(A_raw, h0, out);
}

// round 14
// speedup vs baseline: 21.3035x; 21.3035x over previous
#include <cuda_runtime.h>
#include <math.h>

// Problem constants
#define T_STEPS 16384
#define HDIM    1024
#define XDIM    256

// Recurrent kernel config (R3-proven topology + R3-proven sync)
#define NCTA          128   // persistent CTAs (co-resident in wave 1)
#define ROWS_PER_CTA  8     // HDIM / NCTA
#define RNN_THREADS   256   // 8 warps, one row per warp
#define LINE_INTS     32    // one counter per 128B line
#define WATCHDOG_CYC  400000000LL   // ~0.2 s before abort

// Scratch (device globals: allocation-free per harness rules)
__device__ float g_bx[(size_t)T_STEPS * HDIM];           // Bx_c, 64 MB
__device__ int   g_cnt[(size_t)T_STEPS * LINE_INTS];     // 1 counter/line, 2 MB
__device__ int   g_abort;

// ---------------------------------------------------------------------------
// helpers
// ---------------------------------------------------------------------------
__device__ __forceinline__ int ld_acquire_gpu(const int* p) {
    int v;
    asm volatile("ld.acquire.gpu.global.s32 %0, [%1];" : "=r"(v) : "l"(p) : "memory");
    return v;
}

__device__ __forceinline__ void red_release_add(int* p, int v) {
    asm volatile("red.release.gpu.global.add.s32 [%0], %1;"
                 :: "l"(p), "r"(v) : "memory");
}

__device__ __forceinline__ int ldcg_i32(const int* p) {
    int v;
    asm volatile("ld.global.cg.s32 %0, [%1];" : "=r"(v) : "l"(p) : "memory");
    return v;
}

__device__ __forceinline__ void stg_i32(int* p, int v) {
    asm volatile("st.global.s32 [%0], %1;" :: "l"(p), "r"(v) : "memory");
}

__device__ __forceinline__ void fence_acq() {
    asm volatile("fence.acq_rel.gpu;" ::: "memory");
}

__device__ __forceinline__ float warp_sum(float v) {
#pragma unroll
    for (int s = 16; s > 0; s >>= 1)
        v += __shfl_xor_sync(0xffffffffu, v, s);
    return v;
}

__device__ __forceinline__ float fast_tanh(float x) {
    // tanh(x) = 1 - 2/(exp(2x)+1); MUFU-based, ~1e-6 rel error (validated R11).
    return 1.0f - __fdividef(2.0f, __expf(2.0f * x) + 1.0f);
}

// ---------------------------------------------------------------------------
// 0) zero counters + abort (graph replays reuse device globals -> re-init)
// ---------------------------------------------------------------------------
__global__ void init_cnt_kernel() {
    size_t i = (size_t)blockIdx.x * blockDim.x + threadIdx.x;
    size_t n = (size_t)T_STEPS * LINE_INTS;
    for (size_t k = i; k < n; k += (size_t)gridDim.x * blockDim.x)
        g_cnt[k] = 0;
    if (i == 0) g_abort = 0;
}

// ---------------------------------------------------------------------------
// 1) Bx_c = x_seq @ B^T + c   (T x H), fp32 tiled GEMM
// ---------------------------------------------------------------------------
__global__ __launch_bounds__(256) void gemm_bx_kernel(
    const float* __restrict__ x,   // (T, 256)
    const float* __restrict__ B,   // (1024, 256)
    const float* __restrict__ c)   // (1024,)
{
    __shared__ float xsT[32][132];
    __shared__ float bsT[32][68];

    const int bj  = blockIdx.x * 64;
    const int bt  = blockIdx.y * 128;
    const int tid = threadIdx.x;
    const int tx  = tid & 15;
    const int ty  = tid >> 4;

    float acc[8][4];
#pragma unroll
    for (int i = 0; i < 8; i++)
#pragma unroll
        for (int j = 0; j < 4; j++) acc[i][j] = 0.0f;

    for (int k0 = 0; k0 < XDIM; k0 += 32) {
#pragma unroll
        for (int i = 0; i < 4; i++) {
            int idx = tid + i * 256;
            int r   = idx >> 3;
            int kk4 = (idx & 7) * 4;
            float4 v = *(const float4*)&x[(size_t)(bt + r) * XDIM + k0 + kk4];
            xsT[kk4 + 0][r] = v.x; xsT[kk4 + 1][r] = v.y;
            xsT[kk4 + 2][r] = v.z; xsT[kk4 + 3][r] = v.w;
        }
#pragma unroll
        for (int i = 0; i < 2; i++) {
            int idx = tid + i * 256;
            int r   = idx >> 3;
            int kk4 = (idx & 7) * 4;
            float4 v = *(const float4*)&B[(size_t)(bj + r) * XDIM + k0 + kk4];
            bsT[kk4 + 0][r] = v.x; bsT[kk4 + 1][r] = v.y;
            bsT[kk4 + 2][r] = v.z; bsT[kk4 + 3][r] = v.w;
        }
        __syncthreads();

#pragma unroll
        for (int kk = 0; kk < 32; kk++) {
            float xr[8], br[4];
#pragma unroll
            for (int i = 0; i < 8; i++) xr[i] = xsT[kk][ty * 8 + i];
#pragma unroll
            for (int j = 0; j < 4; j++) br[j] = bsT[kk][tx * 4 + j];
#pragma unroll
            for (int i = 0; i < 8; i++)
#pragma unroll
                for (int j = 0; j < 4; j++)
                    acc[i][j] = fmaf(xr[i], br[j], acc[i][j]);
        }
        __syncthreads();
    }

#pragma unroll
    for (int i = 0; i < 8; i++) {
        int t = bt + ty * 8 + i;
#pragma unroll
        for (int j = 0; j < 4; j++) {
            int col = bj + tx * 4 + j;
            g_bx[(size_t)t * HDIM + col] = acc[i][j] + c[col];
        }
    }
}

// ---------------------------------------------------------------------------
// 2) persistent recurrent kernel: R3 sync verbatim + SMEM h staging.
//    The R3-measured ~4.1k cyc/step hotspot was every warp reading the
//    full 4KB h from L2 (4096 sector-requests per line per step). Here
//    each CTA stages h once (256 coalesced float4 LDGs -> smem), cutting
//    per-line pressure 8x; warps then read conflict-free via LDS.128.
// ---------------------------------------------------------------------------
__global__ __launch_bounds__(RNN_THREADS, 1) void rnn_scan_kernel(
    const float* __restrict__ A_raw,  // (1024, 1024)
    const float* __restrict__ h0,     // (1024,)
    float* __restrict__ out)          // (16384, 1024)
{
    __shared__ float sh[HDIM];        // staged h (4KB)
    __shared__ int s_abort;
    const int b   = blockIdx.x;
    const int w   = threadIdx.x >> 5;
    const int l   = threadIdx.x & 31;
    const int row = b * ROWS_PER_CTA + w;
    const int sidx = (threadIdx.x + 2 * b) & 255;   // staggered stage index

    if (threadIdx.x == 0) s_abort = 0;

    // Load A row segment into registers, applying A = 0.9*I + 0.1*A_raw
    float4 a[8];
#pragma unroll
    for (int i = 0; i < 8; i++) {
        int col  = 32 * l + 4 * i;
        float4 v = *(const float4*)&A_raw[(size_t)row * HDIM + col];
        v.x *= 0.1f; v.y *= 0.1f; v.z *= 0.1f; v.w *= 0.1f;
        int d = row - col;
        if (d == 0) v.x += 0.9f;
        else if (d == 1) v.y += 0.9f;
        else if (d == 2) v.z += 0.9f;
        else if (d == 3) v.w += 0.9f;
        a[i] = v;
    }
    __syncthreads();

    const float* hprev = h0;

    for (int t = 0; t < T_STEPS; t++) {
        // bias prefetch (independent of h -> overlaps wait)
        float bxv = 0.0f;
        if (l == 0) bxv = g_bx[(size_t)t * HDIM + row];

        if (t > 0) {
            if (threadIdx.x == 0) {
                // R3's proven-live heavy poll body (~900cyc period)
                const int* cp = &g_cnt[(size_t)(t - 1) * LINE_INTS];
                long long t0 = clock64();
                for (;;) {
                    if (ld_acquire_gpu(cp) >= NCTA) break;
                    if (ldcg_i32(&g_abort)) { s_abort = 1; break; }
                    if ((clock64() - t0) > WATCHDOG_CYC) {
                        stg_i32(&g_abort, 1);
                        s_abort = 1;
                        break;
                    }
                }
                if (!s_abort) fence_acq();
            }
            __syncthreads();
            if (s_abort) return;   // uniform exit: fallback recomputes
            hprev = out + (size_t)(t - 1) * HDIM;
        }

        // stage h into smem: one float4 per thread, each line read ONCE per CTA
        ((float4*)sh)[sidx] = ((const float4*)hprev)[sidx];
        __syncthreads();

        // dot product from smem: lane l reads sh[32l..32l+31] via LDS.128
        // (phase-groups of 8 lanes hit distinct banks: conflict-free)
        const float4* s4 = (const float4*)(sh + 32 * l);
        float a0 = 0.f, a1 = 0.f, a2 = 0.f, a3 = 0.f;
#pragma unroll
        for (int i = 0; i < 8; i++) {
            float4 hv = s4[i];
            a0 = fmaf(a[i].x, hv.x, a0);
            a1 = fmaf(a[i].y, hv.y, a1);
            a2 = fmaf(a[i].z, hv.z, a2);
            a3 = fmaf(a[i].w, hv.w, a3);
        }
        float acc = warp_sum((a0 + a1) + (a2 + a3));

        if (l == 0) {
            out[(size_t)t * HDIM + row] = fast_tanh(acc + bxv);
        }

        __syncthreads();  // all 8 rows stored (and smem reads done) before arrival
        if (threadIdx.x == 0) {
            red_release_add(&g_cnt[(size_t)t * LINE_INTS], 1);
        }
    }
}

// ---------------------------------------------------------------------------
// 3) fallback: single-CTA full recompute; runs only if g_abort was set.
// ---------------------------------------------------------------------------
__global__ __launch_bounds__(1024) void fallback_scan_kernel(
    const float* __restrict__ A_raw,
    const float* __restrict__ h0,
    float* __restrict__ out)
{
    if (g_abort == 0) return;

    __shared__ float h[HDIM];
    __shared__ float hn[HDIM];
    const int tid = threadIdx.x;
    const int w   = tid >> 5;
    const int l   = tid & 31;

    h[tid] = h0[tid];
    __syncthreads();

    for (int t = 0; t < T_STEPS; t++) {
        for (int r = w; r < HDIM; r += 32) {
            const float* Ar = A_raw + (size_t)r * HDIM;
            float acc = 0.0f;
#pragma unroll 8
            for (int k = l; k < HDIM; k += 32)
                acc = fmaf(Ar[k], h[k], acc);
#pragma unroll
            for (int s = 16; s > 0; s >>= 1)
                acc += __shfl_xor_sync(0xffffffffu, acc, s);
            if (l == 0) {
                float v = tanhf(0.1f * acc + 0.9f * h[r] +
                                g_bx[(size_t)t * HDIM + r]);
                hn[r] = v;
                out[(size_t)t * HDIM + r] = v;
            }
        }
        __syncthreads();
        h[tid] = hn[tid];
        __syncthreads();
    }
}

// ---------------------------------------------------------------------------
// launch
// ---------------------------------------------------------------------------
extern "C" void kernel_launch(void* const* d_in, const int* in_sizes, int n_in,
                              void* d_out, int out_size) {
    const float* x_seq = (const float*)d_in[0];  // (16384, 256)
    const float* h0    = (const float*)d_in[1];  // (1024,)
    const float* A_raw = (const float*)d_in[2];  // (1024, 1024)
    const float* B     = (const float*)d_in[3];  // (1024, 256)
    const float* c     = (const float*)d_in[4];  // (1024,)
    float* out = (float*)d_out;                  // (16384, 1024)

    init_cnt_kernel<<<256, 1024>>>();
    gemm_bx_kernel<<<dim3(HDIM / 64, T_STEPS / 128), 256>>>(x_seq, B, c);
    rnn_scan_kernel<<<NCTA, RNN_THREADS>>>(A_raw, h0, out);
    fallback_scan_kernel<<<1, 1024>>>(A_raw, h0, out);
}

// round 15
// speedup vs baseline: 24.0228x; 1.1276x over previous
#include <cuda_runtime.h>
#include <math.h>

// Problem constants
#define T_STEPS 16384
#define HDIM    1024
#define XDIM    256

// Recurrent kernel config (R3-proven: best measured = 43.7ms)
#define NCTA          128   // persistent CTAs (co-resident in wave 1)
#define ROWS_PER_CTA  8     // HDIM / NCTA
#define RNN_THREADS   256   // 8 warps, one row per warp
#define WATCHDOG_CYC  400000000LL   // ~0.2 s before abort

// Scratch (device globals: allocation-free per harness rules)
__device__ float g_bx[(size_t)T_STEPS * HDIM];   // Bx_c precompute, 64 MB
__device__ int   g_cnt[T_STEPS];                 // packed per-step counters (R3 geometry)
__device__ int   g_abort;

// ---------------------------------------------------------------------------
// helpers
// ---------------------------------------------------------------------------
__device__ __forceinline__ int ld_acquire_gpu(const int* p) {
    int v;
    asm volatile("ld.acquire.gpu.global.s32 %0, [%1];" : "=r"(v) : "l"(p) : "memory");
    return v;
}

__device__ __forceinline__ void red_release_add(int* p, int v) {
    asm volatile("red.release.gpu.global.add.s32 [%0], %1;" :: "l"(p), "r"(v) : "memory");
}

__device__ __forceinline__ int ldcg_i32(const int* p) {
    int v;
    asm volatile("ld.global.cg.s32 %0, [%1];" : "=r"(v) : "l"(p) : "memory");
    return v;
}

__device__ __forceinline__ void stg_i32(int* p, int v) {
    asm volatile("st.global.s32 [%0], %1;" :: "l"(p), "r"(v) : "memory");
}

__device__ __forceinline__ float warp_sum(float v) {
#pragma unroll
    for (int s = 16; s > 0; s >>= 1)
        v += __shfl_xor_sync(0xffffffffu, v, s);
    return v;
}

__device__ __forceinline__ float fast_tanh(float x) {
    // tanh(x) = 1 - 2/(exp(2x)+1); MUFU-based, ~1e-6 rel error (validated R11/R14).
    return 1.0f - __fdividef(2.0f, __expf(2.0f * x) + 1.0f);
}

// ---------------------------------------------------------------------------
// 0) zero counters + abort (graph replays reuse device globals -> re-init)
// ---------------------------------------------------------------------------
__global__ void init_cnt_kernel() {
    int i = blockIdx.x * blockDim.x + threadIdx.x;
    g_cnt[i] = 0;
    if (i == 0) g_abort = 0;
}

// ---------------------------------------------------------------------------
// 1) Bx_c = x_seq @ B^T + c   (T x H), fp32 tiled GEMM
// ---------------------------------------------------------------------------
__global__ __launch_bounds__(256) void gemm_bx_kernel(
    const float* __restrict__ x,   // (T, 256)
    const float* __restrict__ B,   // (1024, 256)
    const float* __restrict__ c)   // (1024,)
{
    __shared__ float xsT[32][132];
    __shared__ float bsT[32][68];

    const int bj  = blockIdx.x * 64;
    const int bt  = blockIdx.y * 128;
    const int tid = threadIdx.x;
    const int tx  = tid & 15;
    const int ty  = tid >> 4;

    float acc[8][4];
#pragma unroll
    for (int i = 0; i < 8; i++)
#pragma unroll
        for (int j = 0; j < 4; j++) acc[i][j] = 0.0f;

    for (int k0 = 0; k0 < XDIM; k0 += 32) {
#pragma unroll
        for (int i = 0; i < 4; i++) {
            int idx = tid + i * 256;
            int r   = idx >> 3;
            int kk4 = (idx & 7) * 4;
            float4 v = *(const float4*)&x[(size_t)(bt + r) * XDIM + k0 + kk4];
            xsT[kk4 + 0][r] = v.x; xsT[kk4 + 1][r] = v.y;
            xsT[kk4 + 2][r] = v.z; xsT[kk4 + 3][r] = v.w;
        }
#pragma unroll
        for (int i = 0; i < 2; i++) {
            int idx = tid + i * 256;
            int r   = idx >> 3;
            int kk4 = (idx & 7) * 4;
            float4 v = *(const float4*)&B[(size_t)(bj + r) * XDIM + k0 + kk4];
            bsT[kk4 + 0][r] = v.x; bsT[kk4 + 1][r] = v.y;
            bsT[kk4 + 2][r] = v.z; bsT[kk4 + 3][r] = v.w;
        }
        __syncthreads();

#pragma unroll
        for (int kk = 0; kk < 32; kk++) {
            float xr[8], br[4];
#pragma unroll
            for (int i = 0; i < 8; i++) xr[i] = xsT[kk][ty * 8 + i];
#pragma unroll
            for (int j = 0; j < 4; j++) br[j] = bsT[kk][tx * 4 + j];
#pragma unroll
            for (int i = 0; i < 8; i++)
#pragma unroll
                for (int j = 0; j < 4; j++)
                    acc[i][j] = fmaf(xr[i], br[j], acc[i][j]);
        }
        __syncthreads();
    }

#pragma unroll
    for (int i = 0; i < 8; i++) {
        int t = bt + ty * 8 + i;
#pragma unroll
        for (int j = 0; j < 4; j++) {
            int col = bj + tx * 4 + j;
            g_bx[(size_t)t * HDIM + col] = acc[i][j] + c[col];
        }
    }
}

// ---------------------------------------------------------------------------
// 2) persistent recurrent kernel: the R3-proven protocol, minus the
//    redundant post-detect fence (ld.acquire + bar.sync already order the
//    h loads for the whole CTA), plus MUFU fast_tanh on the publish path.
//    CTA b owns rows [8b, 8b+8); warp w -> row 8b+w; lane l holds
//    A[row, 32l..32l+31] in registers (A = 0.9*I + 0.1*A_raw folded in).
// ---------------------------------------------------------------------------
__global__ __launch_bounds__(RNN_THREADS, 1) void rnn_scan_kernel(
    const float* __restrict__ A_raw,  // (1024, 1024)
    const float* __restrict__ h0,     // (1024,)
    float* __restrict__ out)          // (16384, 1024)
{
    __shared__ int s_abort;
    const int b   = blockIdx.x;
    const int w   = threadIdx.x >> 5;
    const int l   = threadIdx.x & 31;
    const int row = b * ROWS_PER_CTA + w;

    if (threadIdx.x == 0) s_abort = 0;

    // Load A row segment into registers, applying A = 0.9*I + 0.1*A_raw
    float4 a[8];
#pragma unroll
    for (int i = 0; i < 8; i++) {
        int col  = 32 * l + 4 * i;
        float4 v = *(const float4*)&A_raw[(size_t)row * HDIM + col];
        v.x *= 0.1f; v.y *= 0.1f; v.z *= 0.1f; v.w *= 0.1f;
        int d = row - col;
        if (d == 0) v.x += 0.9f;
        else if (d == 1) v.y += 0.9f;
        else if (d == 2) v.z += 0.9f;
        else if (d == 3) v.w += 0.9f;
        a[i] = v;
    }
    __syncthreads();

    const float* hprev = h0;

    for (int t = 0; t < T_STEPS; t++) {
        // bias prefetch (independent of h -> overlaps poll)
        float bxv = 0.0f;
        if (l == 0) bxv = g_bx[(size_t)t * HDIM + row];

        if (t > 0) {
            if (threadIdx.x == 0) {
                // R3's proven-live heavy poll body (~900cyc period,
                // 0.14 reads/cyc aggregate); acquire load supplies ordering.
                const int* cp = &g_cnt[t - 1];
                long long t0 = clock64();
                for (;;) {
                    if (ld_acquire_gpu(cp) >= NCTA) break;
                    if (ldcg_i32(&g_abort)) { s_abort = 1; break; }
                    if ((clock64() - t0) > WATCHDOG_CYC) {
                        stg_i32(&g_abort, 1);
                        s_abort = 1;
                        break;
                    }
                }
                // (no fence: ld.acquire + bar.sync below order the h loads)
            }
            __syncthreads();
            if (s_abort) return;   // uniform exit: fallback recomputes
            hprev = out + (size_t)(t - 1) * HDIM;
        }

        // dot product: 32 contiguous elements per lane, direct LDG->FMA
        const float4* h4 = (const float4*)(hprev + 32 * l);
        float a0 = 0.f, a1 = 0.f, a2 = 0.f, a3 = 0.f;
#pragma unroll
        for (int i = 0; i < 8; i++) {
            float4 hv = h4[i];
            a0 = fmaf(a[i].x, hv.x, a0);
            a1 = fmaf(a[i].y, hv.y, a1);
            a2 = fmaf(a[i].z, hv.z, a2);
            a3 = fmaf(a[i].w, hv.w, a3);
        }
        float acc = warp_sum((a0 + a1) + (a2 + a3));

        if (l == 0) {
            out[(size_t)t * HDIM + row] = fast_tanh(acc + bxv);
        }

        __syncthreads();  // all 8 rows stored before publishing
        if (threadIdx.x == 0) red_release_add(&g_cnt[t], 1);
    }
}

// ---------------------------------------------------------------------------
// 3) fallback: single-CTA full recompute; runs only if g_abort was set.
// ---------------------------------------------------------------------------
__global__ __launch_bounds__(1024) void fallback_scan_kernel(
    const float* __restrict__ A_raw,
    const float* __restrict__ h0,
    float* __restrict__ out)
{
    if (g_abort == 0) return;

    __shared__ float h[HDIM];
    __shared__ float hn[HDIM];
    const int tid = threadIdx.x;
    const int w   = tid >> 5;
    const int l   = tid & 31;

    h[tid] = h0[tid];
    __syncthreads();

    for (int t = 0; t < T_STEPS; t++) {
        for (int r = w; r < HDIM; r += 32) {
            const float* Ar = A_raw + (size_t)r * HDIM;
            float acc = 0.0f;
#pragma unroll 8
            for (int k = l; k < HDIM; k += 32)
                acc = fmaf(Ar[k], h[k], acc);
#pragma unroll
            for (int s = 16; s > 0; s >>= 1)
                acc += __shfl_xor_sync(0xffffffffu, acc, s);
            if (l == 0) {
                float v = tanhf(0.1f * acc + 0.9f * h[r] +
                                g_bx[(size_t)t * HDIM + r]);
                hn[r] = v;
                out[(size_t)t * HDIM + r] = v;
            }
        }
        __syncthreads();
        h[tid] = hn[tid];
        __syncthreads();
    }
}

// ---------------------------------------------------------------------------
// launch
// ---------------------------------------------------------------------------
extern "C" void kernel_launch(void* const* d_in, const int* in_sizes, int n_in,
                              void* d_out, int out_size) {
    const float* x_seq = (const float*)d_in[0];  // (16384, 256)
    const float* h0    = (const float*)d_in[1];  // (1024,)
    const float* A_raw = (const float*)d_in[2];  // (1024, 1024)
    const float* B     = (const float*)d_in[3];  // (1024, 256)
    const float* c     = (const float*)d_in[4];  // (1024,)
    float* out = (float*)d_out;                  // (16384, 1024)

    init_cnt_kernel<<<16, 1024>>>();
    gemm_bx_kernel<<<dim3(HDIM / 64, T_STEPS / 128), 256>>>(x_seq, B, c);
    rnn_scan_kernel<<<NCTA, RNN_THREADS>>>(A_raw, h0, out);
    fallback_scan_kernel<<<1, 1024>>>(A_raw, h0, out);
}

// round 16
// speedup vs baseline: 38.5097x; 1.6031x over previous
#include <cuda_runtime.h>
#include <math.h>

// Problem constants
#define T_STEPS 16384
#define HDIM    1024
#define XDIM    256

// Recurrent kernel config (R3/R15-proven sync; R16 = coalesced h layout)
#define NCTA          128   // persistent CTAs (co-resident in wave 1)
#define ROWS_PER_CTA  8     // HDIM / NCTA
#define RNN_THREADS   256   // 8 warps, one row per warp
#define WATCHDOG_CYC  400000000LL   // ~0.2 s before abort

// Scratch (device globals: allocation-free per harness rules)
__device__ float g_bx[(size_t)T_STEPS * HDIM];   // Bx_c precompute, 64 MB
__device__ int   g_cnt[T_STEPS];                 // packed per-step counters
__device__ int   g_abort;

// ---------------------------------------------------------------------------
// helpers
// ---------------------------------------------------------------------------
__device__ __forceinline__ int ld_acquire_gpu(const int* p) {
    int v;
    asm volatile("ld.acquire.gpu.global.s32 %0, [%1];" : "=r"(v) : "l"(p) : "memory");
    return v;
}

__device__ __forceinline__ void red_release_add(int* p, int v) {
    asm volatile("red.release.gpu.global.add.s32 [%0], %1;" :: "l"(p), "r"(v) : "memory");
}

__device__ __forceinline__ int ldcg_i32(const int* p) {
    int v;
    asm volatile("ld.global.cg.s32 %0, [%1];" : "=r"(v) : "l"(p) : "memory");
    return v;
}

__device__ __forceinline__ void stg_i32(int* p, int v) {
    asm volatile("st.global.s32 [%0], %1;" :: "l"(p), "r"(v) : "memory");
}

__device__ __forceinline__ float warp_sum(float v) {
#pragma unroll
    for (int s = 16; s > 0; s >>= 1)
        v += __shfl_xor_sync(0xffffffffu, v, s);
    return v;
}

__device__ __forceinline__ float fast_tanh(float x) {
    // tanh(x) = 1 - 2/(exp(2x)+1); MUFU-based, ~1e-6 rel error (validated).
    return 1.0f - __fdividef(2.0f, __expf(2.0f * x) + 1.0f);
}

// ---------------------------------------------------------------------------
// 0) zero counters + abort (graph replays reuse device globals -> re-init)
// ---------------------------------------------------------------------------
__global__ void init_cnt_kernel() {
    int i = blockIdx.x * blockDim.x + threadIdx.x;
    g_cnt[i] = 0;
    if (i == 0) g_abort = 0;
}

// ---------------------------------------------------------------------------
// 1) Bx_c = x_seq @ B^T + c   (T x H), fp32 tiled GEMM
// ---------------------------------------------------------------------------
__global__ __launch_bounds__(256) void gemm_bx_kernel(
    const float* __restrict__ x,   // (T, 256)
    const float* __restrict__ B,   // (1024, 256)
    const float* __restrict__ c)   // (1024,)
{
    __shared__ float xsT[32][132];
    __shared__ float bsT[32][68];

    const int bj  = blockIdx.x * 64;
    const int bt  = blockIdx.y * 128;
    const int tid = threadIdx.x;
    const int tx  = tid & 15;
    const int ty  = tid >> 4;

    float acc[8][4];
#pragma unroll
    for (int i = 0; i < 8; i++)
#pragma unroll
        for (int j = 0; j < 4; j++) acc[i][j] = 0.0f;

    for (int k0 = 0; k0 < XDIM; k0 += 32) {
#pragma unroll
        for (int i = 0; i < 4; i++) {
            int idx = tid + i * 256;
            int r   = idx >> 3;
            int kk4 = (idx & 7) * 4;
            float4 v = *(const float4*)&x[(size_t)(bt + r) * XDIM + k0 + kk4];
            xsT[kk4 + 0][r] = v.x; xsT[kk4 + 1][r] = v.y;
            xsT[kk4 + 2][r] = v.z; xsT[kk4 + 3][r] = v.w;
        }
#pragma unroll
        for (int i = 0; i < 2; i++) {
            int idx = tid + i * 256;
            int r   = idx >> 3;
            int kk4 = (idx & 7) * 4;
            float4 v = *(const float4*)&B[(size_t)(bj + r) * XDIM + k0 + kk4];
            bsT[kk4 + 0][r] = v.x; bsT[kk4 + 1][r] = v.y;
            bsT[kk4 + 2][r] = v.z; bsT[kk4 + 3][r] = v.w;
        }
        __syncthreads();

#pragma unroll
        for (int kk = 0; kk < 32; kk++) {
            float xr[8], br[4];
#pragma unroll
            for (int i = 0; i < 8; i++) xr[i] = xsT[kk][ty * 8 + i];
#pragma unroll
            for (int j = 0; j < 4; j++) br[j] = bsT[kk][tx * 4 + j];
#pragma unroll
            for (int i = 0; i < 8; i++)
#pragma unroll
                for (int j = 0; j < 4; j++)
                    acc[i][j] = fmaf(xr[i], br[j], acc[i][j]);
        }
        __syncthreads();
    }

#pragma unroll
    for (int i = 0; i < 8; i++) {
        int t = bt + ty * 8 + i;
#pragma unroll
        for (int j = 0; j < 4; j++) {
            int col = bj + tx * 4 + j;
            g_bx[(size_t)t * HDIM + col] = acc[i][j] + c[col];
        }
    }
}

// ---------------------------------------------------------------------------
// 2) persistent recurrent kernel: R15 sync + COALESCED h layout.
//    Old layout: lane l read h[32l..32l+31] -> each warp LDG.128 scattered
//    over 32 cache lines (nL=32; 256 L1tex wavefronts/warp/step = the
//    measured ~4.8k cyc/step floor). New layout: lane l owns columns
//    {128i+4l..+3}, so each warp LDG.128 covers ONE contiguous 512B span
//    (nL=4; 32 wavefronts/warp/step). Reduce over lanes is unchanged.
// ---------------------------------------------------------------------------
__global__ __launch_bounds__(RNN_THREADS, 1) void rnn_scan_kernel(
    const float* __restrict__ A_raw,  // (1024, 1024)
    const float* __restrict__ h0,     // (1024,)
    float* __restrict__ out)          // (16384, 1024)
{
    __shared__ int s_abort;
    const int b   = blockIdx.x;
    const int w   = threadIdx.x >> 5;
    const int l   = threadIdx.x & 31;
    const int row = b * ROWS_PER_CTA + w;

    if (threadIdx.x == 0) s_abort = 0;

    // Load A row segment into registers, applying A = 0.9*I + 0.1*A_raw.
    // Lane l holds columns {128i + 4l .. 128i + 4l + 3}, i = 0..7.
    float4 a[8];
#pragma unroll
    for (int i = 0; i < 8; i++) {
        int col  = 128 * i + 4 * l;
        float4 v = *(const float4*)&A_raw[(size_t)row * HDIM + col];
        v.x *= 0.1f; v.y *= 0.1f; v.z *= 0.1f; v.w *= 0.1f;
        int d = row - col;
        if (d == 0) v.x += 0.9f;
        else if (d == 1) v.y += 0.9f;
        else if (d == 2) v.z += 0.9f;
        else if (d == 3) v.w += 0.9f;
        a[i] = v;
    }
    __syncthreads();

    const float* hprev = h0;

    for (int t = 0; t < T_STEPS; t++) {
        // bias prefetch (independent of h -> overlaps poll)
        float bxv = 0.0f;
        if (l == 0) bxv = g_bx[(size_t)t * HDIM + row];

        if (t > 0) {
            if (threadIdx.x == 0) {
                // R3/R15-proven heavy poll body (live at 0.14 reads/cyc).
                const int* cp = &g_cnt[t - 1];
                long long t0 = clock64();
                for (;;) {
                    if (ld_acquire_gpu(cp) >= NCTA) break;
                    if (ldcg_i32(&g_abort)) { s_abort = 1; break; }
                    if ((clock64() - t0) > WATCHDOG_CYC) {
                        stg_i32(&g_abort, 1);
                        s_abort = 1;
                        break;
                    }
                }
            }
            __syncthreads();
            if (s_abort) return;   // uniform exit: fallback recomputes
            hprev = out + (size_t)(t - 1) * HDIM;
        }

        // dot product: coalesced — warp instruction i covers h[128i..128i+127]
        const float4* h4 = (const float4*)hprev;
        float a0 = 0.f, a1 = 0.f, a2 = 0.f, a3 = 0.f;
#pragma unroll
        for (int i = 0; i < 8; i++) {
            float4 hv = h4[32 * i + l];   // contiguous 512B per warp instr
            a0 = fmaf(a[i].x, hv.x, a0);
            a1 = fmaf(a[i].y, hv.y, a1);
            a2 = fmaf(a[i].z, hv.z, a2);
            a3 = fmaf(a[i].w, hv.w, a3);
        }
        float acc = warp_sum((a0 + a1) + (a2 + a3));

        if (l == 0) {
            out[(size_t)t * HDIM + row] = fast_tanh(acc + bxv);
        }

        __syncthreads();  // all 8 rows stored before publishing
        if (threadIdx.x == 0) red_release_add(&g_cnt[t], 1);
    }
}

// ---------------------------------------------------------------------------
// 3) fallback: single-CTA full recompute; runs only if g_abort was set.
// ---------------------------------------------------------------------------
__global__ __launch_bounds__(1024) void fallback_scan_kernel(
    const float* __restrict__ A_raw,
    const float* __restrict__ h0,
    float* __restrict__ out)
{
    if (g_abort == 0) return;

    __shared__ float h[HDIM];
    __shared__ float hn[HDIM];
    const int tid = threadIdx.x;
    const int w   = tid >> 5;
    const int l   = tid & 31;

    h[tid] = h0[tid];
    __syncthreads();

    for (int t = 0; t < T_STEPS; t++) {
        for (int r = w; r < HDIM; r += 32) {
            const float* Ar = A_raw + (size_t)r * HDIM;
            float acc = 0.0f;
#pragma unroll 8
            for (int k = l; k < HDIM; k += 32)
                acc = fmaf(Ar[k], h[k], acc);
#pragma unroll
            for (int s = 16; s > 0; s >>= 1)
                acc += __shfl_xor_sync(0xffffffffu, acc, s);
            if (l == 0) {
                float v = tanhf(0.1f * acc + 0.9f * h[r] +
                                g_bx[(size_t)t * HDIM + r]);
                hn[r] = v;
                out[(size_t)t * HDIM + r] = v;
            }
        }
        __syncthreads();
        h[tid] = hn[tid];
        __syncthreads();
    }
}

// ---------------------------------------------------------------------------
// launch
// ---------------------------------------------------------------------------
extern "C" void kernel_launch(void* const* d_in, const int* in_sizes, int n_in,
                              void* d_out, int out_size) {
    const float* x_seq = (const float*)d_in[0];  // (16384, 256)
    const float* h0    = (const float*)d_in[1];  // (1024,)
    const float* A_raw = (const float*)d_in[2];  // (1024, 1024)
    const float* B     = (const float*)d_in[3];  // (1024, 256)
    const float* c     = (const float*)d_in[4];  // (1024,)
    float* out = (float*)d_out;                  // (16384, 1024)

    init_cnt_kernel<<<16, 1024>>>();
    gemm_bx_kernel<<<dim3(HDIM / 64, T_STEPS / 128), 256>>>(x_seq, B, c);
    rnn_scan_kernel<<<NCTA, RNN_THREADS>>>(A_raw, h0, out);
    fallback_scan_kernel<<<1, 1024>>>(A_raw, h0, out);
}